// round 16
// baseline (speedup 1.0000x reference)
#include <cuda_runtime.h>
#include <cuda_fp16.h>
#include <cstdint>

// NearestEmbed: two-pass HMMA argmin, sync-free candidate filtering.
// Pass 1: single-combo fp16 GEMM ranks codes by s = e2 - 2*xe. Each thread
//         keeps a per-pixel top-3 (values; indices for top-2) in REGISTERS --
//         no atomics, no extra barriers in the stage loop. At the end, one
//         shared atomicMin gives the global per-pixel min; threads push their
//         top-2 entries within margin; if a thread's 3rd-best is also within
//         margin, the pixel falls back to an exact full scan (provably safe).
// Pass 2: exact fp32 rescore (validated: == reference):
//         xe = fmaf over d ascending; d2 = fadd(fadd(x2, fmul(-2,xe)), e2);
//         first-index tie-break via packed (d2,k) atomicMin.
// x2/e2 exact sequential fadd(rn(v*v)) ascending d.

#define DCH 128
#define KCODES 1024
#define HW 4096
#define BATCH 32
#define RES_ELEMS ((size_t)BATCH * DCH * HW)

#define NTHREADS 256
#define MTILE 64
#define NSTAGE 128           // codes per stage
#define NSTAGES 8
#define CAP 32

#define A_SPLIT 16384        // fp16 x tile: 8 chunks x 64px x 32B
#define W_SPLIT 32768        // fp16 w stage: 8 chunks x 128c x 32B

#define OFF_A    0
#define OFF_W    16384       // ring: 2 x 32768 (XF f32 tile overlays here)
#define OFF_XF   16384
#define OFF_E2   81920       // 1024 f32
#define OFF_X2   86016       // 64 f32
#define OFF_MARG 86272       // 64 f32
#define OFF_WMS  86528       // 128 f32
#define OFF_SMIN 87296       // 64 int
#define OFF_BEST 87808       // 64 u64
#define OFF_CNT  88320       // 64 int
#define OFF_CAND 88576       // 64 x CAP u16
#define SMEM_TOTAL 92672

__device__ __align__(16) unsigned char g_wsplit[NSTAGES * W_SPLIT];
__device__ __align__(16) float g_wT[KCODES * DCH];
__device__ float g_e2[KCODES];
__device__ float g_wmax[DCH];

// ---------------- helpers ----------------
__device__ __forceinline__ uint32_t smem_u32(const void* p) {
    uint32_t a;
    asm("{ .reg .u64 t; cvta.to.shared.u64 t, %1; cvt.u32.u64 %0, t; }" : "=r"(a) : "l"(p));
    return a;
}
__device__ __forceinline__ void cp16(uint32_t dst, const void* src) {
    asm volatile("cp.async.cg.shared.global [%0], [%1], 16;" :: "r"(dst), "l"(src) : "memory");
}
#define CP_COMMIT() asm volatile("cp.async.commit_group;" ::: "memory")
#define CP_WAIT(N)  asm volatile("cp.async.wait_group %0;" :: "n"(N) : "memory")

#define LDSM_X4(R0, R1, R2, R3, ADDR) \
    asm volatile("ldmatrix.sync.aligned.m8n8.x4.shared.b16 {%0,%1,%2,%3}, [%4];" \
        : "=r"(R0), "=r"(R1), "=r"(R2), "=r"(R3) : "r"(ADDR))

#define MMA16816(D, A0r, A1r, A2r, A3r, B0, B1) \
    asm volatile("mma.sync.aligned.m16n8k16.row.col.f32.f16.f16.f32 " \
        "{%0,%1,%2,%3}, {%4,%5,%6,%7}, {%8,%9}, {%0,%1,%2,%3};" \
        : "+f"((D)[0]), "+f"((D)[1]), "+f"((D)[2]), "+f"((D)[3]) \
        : "r"(A0r), "r"(A1r), "r"(A2r), "r"(A3r), "r"(B0), "r"(B1))

__device__ __host__ __forceinline__ uint32_t swz16(uint32_t p, uint32_t h) {
    uint32_t r = p >> 2;
    uint32_t col = (((p & 3u) * 2u + h) ^ (r & 7u));
    return r * 128u + col * 16u;
}
__device__ __forceinline__ uint4 pack8(const unsigned short* s) {
    uint4 v;
    v.x = (uint32_t)s[0] | ((uint32_t)s[1] << 16);
    v.y = (uint32_t)s[2] | ((uint32_t)s[3] << 16);
    v.z = (uint32_t)s[4] | ((uint32_t)s[5] << 16);
    v.w = (uint32_t)s[6] | ((uint32_t)s[7] << 16);
    return v;
}

// sorted top-3 insert (values b0<=b1<=b2; indices kept for top-2 only)
__device__ __forceinline__ void ins3(float s, int k,
                                     float& b0, float& b1, float& b2,
                                     int& k0, int& k1) {
    if (s < b2) {
        if (s < b1) {
            b2 = b1;
            if (s < b0) { b1 = b0; k1 = k0; b0 = s; k0 = k; }
            else        { b1 = s; k1 = k; }
        } else {
            b2 = s;
        }
    }
}

// ---------------- prep: e2 + wT + wmax + fp16 w (scaled x1024) ----------------
__global__ void convert_w_kernel(const float* __restrict__ w) {
    __shared__ float wred[DCH];
    const int nt = blockIdx.x;          // stage (128 codes)
    const int c = threadIdx.x;          // 0..127
    const int k = nt * NSTAGE + c;
    wred[c] = 0.0f;
    __syncthreads();
    float e2 = 0.0f;
    for (int g = 0; g < 16; ++g) {
        unsigned short s0[8];
#pragma unroll
        for (int j = 0; j < 8; ++j) {
            int d = g * 8 + j;
            float v = w[(size_t)d * KCODES + k];
            e2 = __fadd_rn(e2, __fmul_rn(v, v));
            g_wT[(size_t)k * DCH + d] = v;
            atomicMax((int*)&wred[d], __float_as_int(fabsf(v)));
            s0[j] = __half_as_ushort(__float2half_rn(v * 1024.0f));
        }
        *(uint4*)(g_wsplit + (size_t)nt * W_SPLIT + (size_t)(g >> 1) * 4096
                  + swz16((uint32_t)c, (uint32_t)(g & 1))) = pack8(s0);
    }
    g_e2[k] = e2;
    __syncthreads();
    atomicMax((int*)&g_wmax[c], __float_as_int(wred[c]));
}

// ---------------- main ----------------
__global__ __launch_bounds__(NTHREADS, 2)
void nearest_embed_2pass_kernel(const float* __restrict__ x,
                                const float* __restrict__ w,
                                float* __restrict__ out,
                                int write_amin) {
    extern __shared__ char smem[];
    const uint32_t su = smem_u32(smem);
    const int tid = threadIdx.x;
    const int blk = blockIdx.x;
    const int b = blk >> 6;
    const int hw0 = (blk & 63) * MTILE;

    float* e2s = (float*)(smem + OFF_E2);
    float* x2s = (float*)(smem + OFF_X2);
    float* margins = (float*)(smem + OFF_MARG);
    float* wms = (float*)(smem + OFF_WMS);
    int* smin = (int*)(smem + OFF_SMIN);
    unsigned long long* best = (unsigned long long*)(smem + OFF_BEST);
    int* cnt = (int*)(smem + OFF_CNT);
    unsigned short* cands = (unsigned short*)(smem + OFF_CAND);

    if (tid < MTILE) {
        best[tid] = 0xFFFFFFFFFFFFFFFFull;
        cnt[tid] = 0;
        smin[tid] = 0x7F800000;
    }
    for (int i = tid; i < KCODES; i += NTHREADS) e2s[i] = g_e2[i];
    if (tid < DCH) wms[tid] = g_wmax[tid];

    // ---- stage x f32 tile [128d][64px] ----
    const float* xbase = x + ((size_t)b * DCH) * HW + hw0;
    for (int t = tid; t < DCH * 16; t += NTHREADS) {
        int d = t >> 4, q = t & 15;
        cp16(su + OFF_XF + (uint32_t)(d * 256 + q * 16),
             xbase + (size_t)d * HW + q * 4);
    }
    CP_COMMIT();
    CP_WAIT(0);
    __syncthreads();

    // ---- x2 (exact) + per-pixel margin ----
    const float* xf = (const float*)(smem + OFF_XF);
    if (tid < MTILE) {
        float a = 0.0f, m = 0.0f;
        for (int d = 0; d < DCH; ++d) {
            float v = xf[d * MTILE + tid];
            a = __fadd_rn(a, __fmul_rn(v, v));
            m = fmaf(fabsf(v), wms[d], m);
        }
        x2s[tid] = a;
        margins[tid] = m * 0.0045f + 2.0e-4f;
    }

    // ---- convert x -> single fp16 tile (swizzled) ----
    {
        const int px = tid & 63;
        const int quarter = tid >> 6;
        for (int g = quarter * 4; g < quarter * 4 + 4; ++g) {
            unsigned short s0[8];
#pragma unroll
            for (int j = 0; j < 8; ++j)
                s0[j] = __half_as_ushort(__float2half_rn(xf[(g * 8 + j) * MTILE + px]));
            *(uint4*)(smem + OFF_A + (g >> 1) * 2048
                      + swz16((uint32_t)px, (uint32_t)(g & 1))) = pack8(s0);
        }
    }
    __syncthreads();   // A ready; XF area (= W ring) reusable

    // ---- prefetch w stage 0 (32KB) ----
    for (int t = tid; t < W_SPLIT / 16; t += NTHREADS)
        cp16(su + OFF_W + (uint32_t)(t * 16), g_wsplit + (size_t)t * 16);
    CP_COMMIT();

    // ---- fragment addressing ----
    const int lane = tid & 31;
    const int warp = tid >> 5;
    const int pg = warp >> 1;
    const int chalf = warp & 1;       // 64 of 128 codes per stage
    const int px0 = pg * 16;
    const int pxA = px0 + (lane >> 2);
    const int pxB = pxA + 8;

    const uint32_t ap = (uint32_t)(px0 + (lane & 7) + ((lane >> 3) & 1) * 8);
    const uint32_t ah = (uint32_t)(lane >> 4);
    const uint32_t aoff = swz16(ap, ah);
    const uint32_t bc = (uint32_t)((lane & 7) + ((lane >> 4) & 1) * 8);
    const uint32_t bh = (uint32_t)((lane >> 3) & 1);
    uint32_t boff[4];
#pragma unroll
    for (int ct = 0; ct < 4; ++ct)
        boff[ct] = swz16((uint32_t)(chalf * 64 + ct * 16) + bc, bh);

    // ---- hoist A fragments (32 regs) ----
    uint32_t Ar[32];
#pragma unroll
    for (int ch = 0; ch < 8; ++ch)
        LDSM_X4(Ar[ch * 4 + 0], Ar[ch * 4 + 1], Ar[ch * 4 + 2], Ar[ch * 4 + 3],
                su + OFF_A + ch * 2048 + aoff);

    const float MA = margins[pxA];
    const float MB = margins[pxB];

    float acc[8][4];
#pragma unroll
    for (int t = 0; t < 8; ++t)
#pragma unroll
        for (int q = 0; q < 4; ++q) acc[t][q] = 0.0f;

    const float FINF = __int_as_float(0x7F800000);
    float a0 = FINF, a1 = FINF, a2 = FINF;   // pixel A top-3
    float c0 = FINF, c1 = FINF, c2 = FINF;   // pixel B top-3
    int ka0 = 0, ka1 = 0, kb0 = 0, kb1 = 0;

    // ================= PASS 1 (sync-light) =================
    for (int nt = 0; nt < NSTAGES; ++nt) {
        CP_WAIT(0);
        __syncthreads();   // stage nt visible; prev stage's reads done

        if (nt + 1 < NSTAGES) {
            const unsigned char* src = g_wsplit + (size_t)(nt + 1) * W_SPLIT;
            const uint32_t dst = su + OFF_W + ((nt + 1) & 1) * W_SPLIT;
            for (int t = tid; t < W_SPLIT / 16; t += NTHREADS)
                cp16(dst + (uint32_t)(t * 16), src + (size_t)t * 16);
            CP_COMMIT();
        }

        const uint32_t wb = su + OFF_W + (nt & 1) * W_SPLIT;

#pragma unroll
        for (int ch = 0; ch < 8; ++ch) {
            uint32_t B0[4], B1[4], B2[4], B3[4];
            LDSM_X4(B0[0], B0[1], B0[2], B0[3], wb + ch * 4096 + boff[0]);
            LDSM_X4(B1[0], B1[1], B1[2], B1[3], wb + ch * 4096 + boff[1]);
            LDSM_X4(B2[0], B2[1], B2[2], B2[3], wb + ch * 4096 + boff[2]);
            LDSM_X4(B3[0], B3[1], B3[2], B3[3], wb + ch * 4096 + boff[3]);
            MMA16816(acc[0], Ar[ch * 4 + 0], Ar[ch * 4 + 1], Ar[ch * 4 + 2], Ar[ch * 4 + 3], B0[0], B0[1]);
            MMA16816(acc[1], Ar[ch * 4 + 0], Ar[ch * 4 + 1], Ar[ch * 4 + 2], Ar[ch * 4 + 3], B0[2], B0[3]);
            MMA16816(acc[2], Ar[ch * 4 + 0], Ar[ch * 4 + 1], Ar[ch * 4 + 2], Ar[ch * 4 + 3], B1[0], B1[1]);
            MMA16816(acc[3], Ar[ch * 4 + 0], Ar[ch * 4 + 1], Ar[ch * 4 + 2], Ar[ch * 4 + 3], B1[2], B1[3]);
            MMA16816(acc[4], Ar[ch * 4 + 0], Ar[ch * 4 + 1], Ar[ch * 4 + 2], Ar[ch * 4 + 3], B2[0], B2[1]);
            MMA16816(acc[5], Ar[ch * 4 + 0], Ar[ch * 4 + 1], Ar[ch * 4 + 2], Ar[ch * 4 + 3], B2[2], B2[3]);
            MMA16816(acc[6], Ar[ch * 4 + 0], Ar[ch * 4 + 1], Ar[ch * 4 + 2], Ar[ch * 4 + 3], B3[0], B3[1]);
            MMA16816(acc[7], Ar[ch * 4 + 0], Ar[ch * 4 + 1], Ar[ch * 4 + 2], Ar[ch * 4 + 3], B3[2], B3[3]);
        }

        // ---- epilogue: s = e2 - 2*xe; register top-3 insert, no sync ----
        const int kq = nt * NSTAGE + chalf * 64 + (lane & 3) * 2;
#pragma unroll
        for (int t = 0; t < 8; ++t)
#pragma unroll
            for (int q = 0; q < 4; ++q) {
                const int kk = kq + t * 8 + (q & 1);
                float s = __fadd_rn(e2s[kk], __fmul_rn(-0.001953125f, acc[t][q]));
                if (q < 2) ins3(s, kk, a0, a1, a2, ka0, ka1);
                else       ins3(s, kk, c0, c1, c2, kb0, kb1);
                acc[t][q] = 0.0f;
            }
    }

    // ---- global per-pixel min, then threshold push (single sync point) ----
    atomicMin(&smin[pxA], __float_as_int(a0 + 4.0f));
    atomicMin(&smin[pxB], __float_as_int(c0 + 4.0f));
    __syncthreads();
    {
        const float thrA = __int_as_float(smin[pxA]) - 4.0f + MA;
        const float thrB = __int_as_float(smin[pxB]) - 4.0f + MB;
        if (a2 <= thrA) {                 // 3rd-best also qualifies -> fallback
            atomicAdd(&cnt[pxA], 10000);
        } else {
            if (a0 <= thrA) {
                int slot = atomicAdd(&cnt[pxA], 1);
                if (slot < CAP) cands[pxA * CAP + slot] = (unsigned short)ka0;
            }
            if (a1 <= thrA) {
                int slot = atomicAdd(&cnt[pxA], 1);
                if (slot < CAP) cands[pxA * CAP + slot] = (unsigned short)ka1;
            }
        }
        if (c2 <= thrB) {
            atomicAdd(&cnt[pxB], 10000);
        } else {
            if (c0 <= thrB) {
                int slot = atomicAdd(&cnt[pxB], 1);
                if (slot < CAP) cands[pxB * CAP + slot] = (unsigned short)kb0;
            }
            if (c1 <= thrB) {
                int slot = atomicAdd(&cnt[pxB], 1);
                if (slot < CAP) cands[pxB * CAP + slot] = (unsigned short)kb1;
            }
        }
    }

    // ================= PASS 2: exact rescore =================
    __syncthreads();
    for (int t = tid; t < DCH * 16; t += NTHREADS) {   // reload x f32 tile
        int d = t >> 4, q = t & 15;
        cp16(su + OFF_XF + (uint32_t)(d * 256 + q * 16),
             xbase + (size_t)d * HW + q * 4);
    }
    CP_COMMIT();
    CP_WAIT(0);
    __syncthreads();

    {
        const float* xf2 = (const float*)(smem + OFF_XF);
        const int px = tid >> 2, th = tid & 3;
        const int cv = cnt[px];
        const float x2v = x2s[px];
        const int lim = (cv <= CAP) ? cv : KCODES;
        for (int i = th; i < lim; i += 4) {
            const int k = (cv <= CAP) ? cands[px * CAP + i] : i;
            const float* wrow = g_wT + (size_t)k * DCH;
            float xe = 0.0f;
#pragma unroll 8
            for (int d = 0; d < DCH; ++d)
                xe = fmaf(xf2[d * MTILE + px], __ldg(wrow + d), xe);
            float d2 = __fadd_rn(__fadd_rn(x2v, __fmul_rn(-2.0f, xe)), e2s[k]);
            unsigned long long pk =
                ((unsigned long long)__float_as_uint(d2) << 32) | (unsigned)k;
            atomicMin(&best[px], pk);
        }
    }
    __syncthreads();

    // ---- outputs: gather codebook rows + argmin ----
    const size_t obase = ((size_t)b * DCH) * HW + hw0;
    for (int t = tid; t < DCH * MTILE; t += NTHREADS) {
        int d = t >> 6;
        int px = t & 63;
        unsigned k = (unsigned)(best[px] & 0xFFFFFFFFu);
        out[obase + (size_t)d * HW + px] = w[(size_t)d * KCODES + k];
    }
    if (write_amin && tid < MTILE) {
        unsigned k = (unsigned)(best[tid] & 0xFFFFFFFFu);
        out[RES_ELEMS + (size_t)b * HW + hw0 + tid] = (float)k;
    }
}

extern "C" void kernel_launch(void* const* d_in, const int* in_sizes, int n_in,
                              void* d_out, int out_size) {
    const float* x = (const float*)d_in[0];
    const float* w = (const float*)d_in[1];
    float* out = (float*)d_out;
    const int write_amin = ((size_t)out_size > RES_ELEMS) ? 1 : 0;

    cudaFuncSetAttribute(nearest_embed_2pass_kernel,
                         cudaFuncAttributeMaxDynamicSharedMemorySize, SMEM_TOTAL);

    convert_w_kernel<<<NSTAGES, NSTAGE>>>(w);
    nearest_embed_2pass_kernel<<<(BATCH * HW) / MTILE, NTHREADS, SMEM_TOTAL>>>(
        x, w, out, write_amin);
}

// round 17
// speedup vs baseline: 1.0272x; 1.0272x over previous
#include <cuda_runtime.h>
#include <cuda_fp16.h>
#include <cstdint>

// NearestEmbed: two-pass HMMA argmin, sync-free + BRANCH-FREE candidate filter.
// Pass 1: single-combo fp16 GEMM ranks codes by s = e2 - 2*xe. Each thread
//         keeps a per-pixel top-3 in registers via branch-free min/max/select
//         (R16's nested-branch insert caused BSSY/BSYNC serialization).
// Pass 2: exact fp32 rescore (validated == reference):
//         xe = fmaf over d ascending; d2 = fadd(fadd(x2, fmul(-2,xe)), e2);
//         first-index tie-break via packed (d2,k) atomicMin.
// x2/e2 exact sequential fadd(rn(v*v)) ascending d.

#define DCH 128
#define KCODES 1024
#define HW 4096
#define BATCH 32
#define RES_ELEMS ((size_t)BATCH * DCH * HW)

#define NTHREADS 256
#define MTILE 64
#define NSTAGE 128           // codes per stage
#define NSTAGES 8
#define CAP 32

#define A_SPLIT 16384        // fp16 x tile: 8 chunks x 64px x 32B
#define W_SPLIT 32768        // fp16 w stage: 8 chunks x 128c x 32B

#define OFF_A    0
#define OFF_W    16384       // ring: 2 x 32768 (XF f32 tile overlays here)
#define OFF_XF   16384
#define OFF_E2   81920       // 1024 f32
#define OFF_X2   86016       // 64 f32
#define OFF_MARG 86272       // 64 f32
#define OFF_WMS  86528       // 128 f32
#define OFF_SMIN 87296       // 64 int
#define OFF_BEST 87808       // 64 u64
#define OFF_CNT  88320       // 64 int
#define OFF_CAND 88576       // 64 x CAP u16
#define SMEM_TOTAL 92672

__device__ __align__(16) unsigned char g_wsplit[NSTAGES * W_SPLIT];
__device__ __align__(16) float g_wT[KCODES * DCH];
__device__ float g_e2[KCODES];
__device__ float g_wmax[DCH];

// ---------------- helpers ----------------
__device__ __forceinline__ uint32_t smem_u32(const void* p) {
    uint32_t a;
    asm("{ .reg .u64 t; cvta.to.shared.u64 t, %1; cvt.u32.u64 %0, t; }" : "=r"(a) : "l"(p));
    return a;
}
__device__ __forceinline__ void cp16(uint32_t dst, const void* src) {
    asm volatile("cp.async.cg.shared.global [%0], [%1], 16;" :: "r"(dst), "l"(src) : "memory");
}
#define CP_COMMIT() asm volatile("cp.async.commit_group;" ::: "memory")
#define CP_WAIT(N)  asm volatile("cp.async.wait_group %0;" :: "n"(N) : "memory")

#define LDSM_X4(R0, R1, R2, R3, ADDR) \
    asm volatile("ldmatrix.sync.aligned.m8n8.x4.shared.b16 {%0,%1,%2,%3}, [%4];" \
        : "=r"(R0), "=r"(R1), "=r"(R2), "=r"(R3) : "r"(ADDR))

#define MMA16816(D, A0r, A1r, A2r, A3r, B0, B1) \
    asm volatile("mma.sync.aligned.m16n8k16.row.col.f32.f16.f16.f32 " \
        "{%0,%1,%2,%3}, {%4,%5,%6,%7}, {%8,%9}, {%0,%1,%2,%3};" \
        : "+f"((D)[0]), "+f"((D)[1]), "+f"((D)[2]), "+f"((D)[3]) \
        : "r"(A0r), "r"(A1r), "r"(A2r), "r"(A3r), "r"(B0), "r"(B1))

__device__ __host__ __forceinline__ uint32_t swz16(uint32_t p, uint32_t h) {
    uint32_t r = p >> 2;
    uint32_t col = (((p & 3u) * 2u + h) ^ (r & 7u));
    return r * 128u + col * 16u;
}
__device__ __forceinline__ uint4 pack8(const unsigned short* s) {
    uint4 v;
    v.x = (uint32_t)s[0] | ((uint32_t)s[1] << 16);
    v.y = (uint32_t)s[2] | ((uint32_t)s[3] << 16);
    v.z = (uint32_t)s[4] | ((uint32_t)s[5] << 16);
    v.w = (uint32_t)s[6] | ((uint32_t)s[7] << 16);
    return v;
}

// BRANCH-FREE sorted top-3 insert (b0<=b1<=b2; indices for top-2).
// Verified: s<b0 | b0<=s<b1 | b1<=s<b2 | s>=b2 | ties (strict < keeps first k).
__device__ __forceinline__ void ins3(float s, int k,
                                     float& b0, float& b1, float& b2,
                                     int& k0, int& k1) {
    const bool p0 = s < b0;
    const bool p1 = s < b1;
    b2 = fminf(b2, fmaxf(b1, s));
    b1 = fminf(b1, fmaxf(b0, s));
    k1 = p0 ? k0 : (p1 ? k : k1);
    b0 = fminf(b0, s);
    k0 = p0 ? k : k0;
}

// ---------------- prep: e2 + wT + wmax + fp16 w (scaled x1024) ----------------
__global__ void convert_w_kernel(const float* __restrict__ w) {
    __shared__ float wred[DCH];
    const int nt = blockIdx.x;          // stage (128 codes)
    const int c = threadIdx.x;          // 0..127
    const int k = nt * NSTAGE + c;
    wred[c] = 0.0f;
    __syncthreads();
    float e2 = 0.0f;
    for (int g = 0; g < 16; ++g) {
        unsigned short s0[8];
#pragma unroll
        for (int j = 0; j < 8; ++j) {
            int d = g * 8 + j;
            float v = w[(size_t)d * KCODES + k];
            e2 = __fadd_rn(e2, __fmul_rn(v, v));
            g_wT[(size_t)k * DCH + d] = v;
            atomicMax((int*)&wred[d], __float_as_int(fabsf(v)));
            s0[j] = __half_as_ushort(__float2half_rn(v * 1024.0f));
        }
        *(uint4*)(g_wsplit + (size_t)nt * W_SPLIT + (size_t)(g >> 1) * 4096
                  + swz16((uint32_t)c, (uint32_t)(g & 1))) = pack8(s0);
    }
    g_e2[k] = e2;
    __syncthreads();
    atomicMax((int*)&g_wmax[c], __float_as_int(wred[c]));
}

// ---------------- main ----------------
__global__ __launch_bounds__(NTHREADS, 2)
void nearest_embed_2pass_kernel(const float* __restrict__ x,
                                const float* __restrict__ w,
                                float* __restrict__ out,
                                int write_amin) {
    extern __shared__ char smem[];
    const uint32_t su = smem_u32(smem);
    const int tid = threadIdx.x;
    const int blk = blockIdx.x;
    const int b = blk >> 6;
    const int hw0 = (blk & 63) * MTILE;

    float* e2s = (float*)(smem + OFF_E2);
    float* x2s = (float*)(smem + OFF_X2);
    float* margins = (float*)(smem + OFF_MARG);
    float* wms = (float*)(smem + OFF_WMS);
    int* smin = (int*)(smem + OFF_SMIN);
    unsigned long long* best = (unsigned long long*)(smem + OFF_BEST);
    int* cnt = (int*)(smem + OFF_CNT);
    unsigned short* cands = (unsigned short*)(smem + OFF_CAND);

    if (tid < MTILE) {
        best[tid] = 0xFFFFFFFFFFFFFFFFull;
        cnt[tid] = 0;
        smin[tid] = 0x7F800000;
    }
    for (int i = tid; i < KCODES; i += NTHREADS) e2s[i] = g_e2[i];
    if (tid < DCH) wms[tid] = g_wmax[tid];

    // ---- stage x f32 tile [128d][64px] ----
    const float* xbase = x + ((size_t)b * DCH) * HW + hw0;
    for (int t = tid; t < DCH * 16; t += NTHREADS) {
        int d = t >> 4, q = t & 15;
        cp16(su + OFF_XF + (uint32_t)(d * 256 + q * 16),
             xbase + (size_t)d * HW + q * 4);
    }
    CP_COMMIT();
    CP_WAIT(0);
    __syncthreads();

    // ---- x2 (exact) + per-pixel margin ----
    const float* xf = (const float*)(smem + OFF_XF);
    if (tid < MTILE) {
        float a = 0.0f, m = 0.0f;
        for (int d = 0; d < DCH; ++d) {
            float v = xf[d * MTILE + tid];
            a = __fadd_rn(a, __fmul_rn(v, v));
            m = fmaf(fabsf(v), wms[d], m);
        }
        x2s[tid] = a;
        margins[tid] = m * 0.0045f + 2.0e-4f;
    }

    // ---- convert x -> single fp16 tile (swizzled) ----
    {
        const int px = tid & 63;
        const int quarter = tid >> 6;
        for (int g = quarter * 4; g < quarter * 4 + 4; ++g) {
            unsigned short s0[8];
#pragma unroll
            for (int j = 0; j < 8; ++j)
                s0[j] = __half_as_ushort(__float2half_rn(xf[(g * 8 + j) * MTILE + px]));
            *(uint4*)(smem + OFF_A + (g >> 1) * 2048
                      + swz16((uint32_t)px, (uint32_t)(g & 1))) = pack8(s0);
        }
    }
    __syncthreads();   // A ready; XF area (= W ring) reusable

    // ---- prefetch w stage 0 (32KB) ----
    for (int t = tid; t < W_SPLIT / 16; t += NTHREADS)
        cp16(su + OFF_W + (uint32_t)(t * 16), g_wsplit + (size_t)t * 16);
    CP_COMMIT();

    // ---- fragment addressing ----
    const int lane = tid & 31;
    const int warp = tid >> 5;
    const int pg = warp >> 1;
    const int chalf = warp & 1;       // 64 of 128 codes per stage
    const int px0 = pg * 16;
    const int pxA = px0 + (lane >> 2);
    const int pxB = pxA + 8;

    const uint32_t ap = (uint32_t)(px0 + (lane & 7) + ((lane >> 3) & 1) * 8);
    const uint32_t ah = (uint32_t)(lane >> 4);
    const uint32_t aoff = swz16(ap, ah);
    const uint32_t bc = (uint32_t)((lane & 7) + ((lane >> 4) & 1) * 8);
    const uint32_t bh = (uint32_t)((lane >> 3) & 1);
    uint32_t boff[4];
#pragma unroll
    for (int ct = 0; ct < 4; ++ct)
        boff[ct] = swz16((uint32_t)(chalf * 64 + ct * 16) + bc, bh);

    // ---- hoist A fragments (32 regs) ----
    uint32_t Ar[32];
#pragma unroll
    for (int ch = 0; ch < 8; ++ch)
        LDSM_X4(Ar[ch * 4 + 0], Ar[ch * 4 + 1], Ar[ch * 4 + 2], Ar[ch * 4 + 3],
                su + OFF_A + ch * 2048 + aoff);

    const float MA = margins[pxA];
    const float MB = margins[pxB];

    float acc[8][4];
#pragma unroll
    for (int t = 0; t < 8; ++t)
#pragma unroll
        for (int q = 0; q < 4; ++q) acc[t][q] = 0.0f;

    const float FINF = __int_as_float(0x7F800000);
    float a0 = FINF, a1 = FINF, a2 = FINF;   // pixel A top-3
    float c0 = FINF, c1 = FINF, c2 = FINF;   // pixel B top-3
    int ka0 = 0, ka1 = 0, kb0 = 0, kb1 = 0;

    // ================= PASS 1 (sync-light, branch-free epilogue) ============
    for (int nt = 0; nt < NSTAGES; ++nt) {
        CP_WAIT(0);
        __syncthreads();   // stage nt visible; prev stage's reads done

        if (nt + 1 < NSTAGES) {
            const unsigned char* src = g_wsplit + (size_t)(nt + 1) * W_SPLIT;
            const uint32_t dst = su + OFF_W + ((nt + 1) & 1) * W_SPLIT;
            for (int t = tid; t < W_SPLIT / 16; t += NTHREADS)
                cp16(dst + (uint32_t)(t * 16), src + (size_t)t * 16);
            CP_COMMIT();
        }

        const uint32_t wb = su + OFF_W + (nt & 1) * W_SPLIT;

#pragma unroll
        for (int ch = 0; ch < 8; ++ch) {
            uint32_t B0[4], B1[4], B2[4], B3[4];
            LDSM_X4(B0[0], B0[1], B0[2], B0[3], wb + ch * 4096 + boff[0]);
            LDSM_X4(B1[0], B1[1], B1[2], B1[3], wb + ch * 4096 + boff[1]);
            LDSM_X4(B2[0], B2[1], B2[2], B2[3], wb + ch * 4096 + boff[2]);
            LDSM_X4(B3[0], B3[1], B3[2], B3[3], wb + ch * 4096 + boff[3]);
            MMA16816(acc[0], Ar[ch * 4 + 0], Ar[ch * 4 + 1], Ar[ch * 4 + 2], Ar[ch * 4 + 3], B0[0], B0[1]);
            MMA16816(acc[1], Ar[ch * 4 + 0], Ar[ch * 4 + 1], Ar[ch * 4 + 2], Ar[ch * 4 + 3], B0[2], B0[3]);
            MMA16816(acc[2], Ar[ch * 4 + 0], Ar[ch * 4 + 1], Ar[ch * 4 + 2], Ar[ch * 4 + 3], B1[0], B1[1]);
            MMA16816(acc[3], Ar[ch * 4 + 0], Ar[ch * 4 + 1], Ar[ch * 4 + 2], Ar[ch * 4 + 3], B1[2], B1[3]);
            MMA16816(acc[4], Ar[ch * 4 + 0], Ar[ch * 4 + 1], Ar[ch * 4 + 2], Ar[ch * 4 + 3], B2[0], B2[1]);
            MMA16816(acc[5], Ar[ch * 4 + 0], Ar[ch * 4 + 1], Ar[ch * 4 + 2], Ar[ch * 4 + 3], B2[2], B2[3]);
            MMA16816(acc[6], Ar[ch * 4 + 0], Ar[ch * 4 + 1], Ar[ch * 4 + 2], Ar[ch * 4 + 3], B3[0], B3[1]);
            MMA16816(acc[7], Ar[ch * 4 + 0], Ar[ch * 4 + 1], Ar[ch * 4 + 2], Ar[ch * 4 + 3], B3[2], B3[3]);
        }

        // ---- epilogue: s = e2 - 2*xe; branch-free top-3 insert ----
        const int kq = nt * NSTAGE + chalf * 64 + (lane & 3) * 2;
#pragma unroll
        for (int t = 0; t < 8; ++t)
#pragma unroll
            for (int q = 0; q < 4; ++q) {
                const int kk = kq + t * 8 + (q & 1);
                float s = __fadd_rn(e2s[kk], __fmul_rn(-0.001953125f, acc[t][q]));
                if (q < 2) ins3(s, kk, a0, a1, a2, ka0, ka1);
                else       ins3(s, kk, c0, c1, c2, kb0, kb1);
                acc[t][q] = 0.0f;
            }
    }

    // ---- global per-pixel min, then threshold push (single sync point) ----
    atomicMin(&smin[pxA], __float_as_int(a0 + 4.0f));
    atomicMin(&smin[pxB], __float_as_int(c0 + 4.0f));
    __syncthreads();
    {
        const float thrA = __int_as_float(smin[pxA]) - 4.0f + MA;
        const float thrB = __int_as_float(smin[pxB]) - 4.0f + MB;
        if (a2 <= thrA) {                 // 3rd-best also qualifies -> fallback
            atomicAdd(&cnt[pxA], 10000);
        } else {
            if (a0 <= thrA) {
                int slot = atomicAdd(&cnt[pxA], 1);
                if (slot < CAP) cands[pxA * CAP + slot] = (unsigned short)ka0;
            }
            if (a1 <= thrA) {
                int slot = atomicAdd(&cnt[pxA], 1);
                if (slot < CAP) cands[pxA * CAP + slot] = (unsigned short)ka1;
            }
        }
        if (c2 <= thrB) {
            atomicAdd(&cnt[pxB], 10000);
        } else {
            if (c0 <= thrB) {
                int slot = atomicAdd(&cnt[pxB], 1);
                if (slot < CAP) cands[pxB * CAP + slot] = (unsigned short)kb0;
            }
            if (c1 <= thrB) {
                int slot = atomicAdd(&cnt[pxB], 1);
                if (slot < CAP) cands[pxB * CAP + slot] = (unsigned short)kb1;
            }
        }
    }

    // ================= PASS 2: exact rescore =================
    __syncthreads();
    for (int t = tid; t < DCH * 16; t += NTHREADS) {   // reload x f32 tile
        int d = t >> 4, q = t & 15;
        cp16(su + OFF_XF + (uint32_t)(d * 256 + q * 16),
             xbase + (size_t)d * HW + q * 4);
    }
    CP_COMMIT();
    CP_WAIT(0);
    __syncthreads();

    {
        const float* xf2 = (const float*)(smem + OFF_XF);
        const int px = tid >> 2, th = tid & 3;
        const int cv = cnt[px];
        const float x2v = x2s[px];
        const int lim = (cv <= CAP) ? cv : KCODES;
        for (int i = th; i < lim; i += 4) {
            const int k = (cv <= CAP) ? cands[px * CAP + i] : i;
            const float* wrow = g_wT + (size_t)k * DCH;
            float xe = 0.0f;
#pragma unroll 8
            for (int d = 0; d < DCH; ++d)
                xe = fmaf(xf2[d * MTILE + px], __ldg(wrow + d), xe);
            float d2 = __fadd_rn(__fadd_rn(x2v, __fmul_rn(-2.0f, xe)), e2s[k]);
            unsigned long long pk =
                ((unsigned long long)__float_as_uint(d2) << 32) | (unsigned)k;
            atomicMin(&best[px], pk);
        }
    }
    __syncthreads();

    // ---- outputs: gather codebook rows + argmin ----
    const size_t obase = ((size_t)b * DCH) * HW + hw0;
    for (int t = tid; t < DCH * MTILE; t += NTHREADS) {
        int d = t >> 6;
        int px = t & 63;
        unsigned k = (unsigned)(best[px] & 0xFFFFFFFFu);
        out[obase + (size_t)d * HW + px] = w[(size_t)d * KCODES + k];
    }
    if (write_amin && tid < MTILE) {
        unsigned k = (unsigned)(best[tid] & 0xFFFFFFFFu);
        out[RES_ELEMS + (size_t)b * HW + hw0 + tid] = (float)k;
    }
}

extern "C" void kernel_launch(void* const* d_in, const int* in_sizes, int n_in,
                              void* d_out, int out_size) {
    const float* x = (const float*)d_in[0];
    const float* w = (const float*)d_in[1];
    float* out = (float*)d_out;
    const int write_amin = ((size_t)out_size > RES_ELEMS) ? 1 : 0;

    cudaFuncSetAttribute(nearest_embed_2pass_kernel,
                         cudaFuncAttributeMaxDynamicSharedMemorySize, SMEM_TOTAL);

    convert_w_kernel<<<NSTAGES, NSTAGE>>>(w);
    nearest_embed_2pass_kernel<<<(BATCH * HW) / MTILE, NTHREADS, SMEM_TOTAL>>>(
        x, w, out, write_amin);
}